// round 1
// baseline (speedup 1.0000x reference)
#include <cuda_runtime.h>
#include <cuda_bf16.h>
#include <mma.h>

using namespace nvcuda;

#define B_ 8
#define S_ 2048
#define E_ 1024

// ---------------- scratch (device globals: allocation-free rule) ----------------
// packed bf16x2 per element: .x = hi, .y = lo  (x = hi + lo, |x-hi-lo| <~ 2^-16 |x|)
__device__ __nv_bfloat162 g_Q[(size_t)B_ * S_ * E_];   // also reused as attn output
__device__ __nv_bfloat162 g_K[(size_t)B_ * S_ * E_];
__device__ __nv_bfloat162 g_V[(size_t)B_ * S_ * E_];
__device__ __nv_bfloat162 g_W[(size_t)E_ * E_];
__device__ float          g_scores[(size_t)B_ * S_ * S_]; // overwritten in place by packed probs

// ---------------- helpers ----------------
__device__ __forceinline__ unsigned split_pack(float f) {
    __nv_bfloat16 h = __float2bfloat16(f);
    float r = f - __bfloat162float(h);
    __nv_bfloat16 l = __float2bfloat16(r);
    return (unsigned)__bfloat16_as_ushort(h) | ((unsigned)__bfloat16_as_ushort(l) << 16);
}

// ---------------- split kernel: f32 -> packed bf16 hi/lo ----------------
__global__ void __launch_bounds__(256) split_kernel(const float* __restrict__ x,
                                                    unsigned* __restrict__ y, int n4) {
    int i = blockIdx.x * blockDim.x + threadIdx.x;
    if (i >= n4) return;
    float4 v = reinterpret_cast<const float4*>(x)[i];
    uint4 o;
    o.x = split_pack(v.x);
    o.y = split_pack(v.y);
    o.z = split_pack(v.z);
    o.w = split_pack(v.w);
    reinterpret_cast<uint4*>(y)[i] = o;
}

// ---------------- softmax * dropout_mask, in place (f32 scores -> packed bf16x2 probs) ----
__global__ void __launch_bounds__(256) softmax_mask_kernel(
    float* __restrict__ scores, const float* __restrict__ mask,
    const int* __restrict__ sc) {
    __shared__ float redmax[8];
    __shared__ float redsum[8];
    size_t row = blockIdx.x;
    float* srow = scores + row * (size_t)S_;
    const float* mrow = mask + row * (size_t)S_;
    int t = threadIdx.x;
    int lane = t & 31, warp = t >> 5;

    int iv = *sc;
    float denom = (iv == 32) ? 32.0f : __int_as_float(iv); // robust to int32 or f32 storage
    float scale = 1.0f / denom;

    float v[8];
#pragma unroll
    for (int j = 0; j < 8; j++) v[j] = srow[t + 256 * j] * scale;

    float m = v[0];
#pragma unroll
    for (int j = 1; j < 8; j++) m = fmaxf(m, v[j]);
#pragma unroll
    for (int o = 16; o; o >>= 1) m = fmaxf(m, __shfl_xor_sync(0xffffffffu, m, o));
    if (lane == 0) redmax[warp] = m;
    __syncthreads();
    float bm = redmax[0];
#pragma unroll
    for (int w = 1; w < 8; w++) bm = fmaxf(bm, redmax[w]);

    float e[8], s = 0.f;
#pragma unroll
    for (int j = 0; j < 8; j++) { e[j] = __expf(v[j] - bm); s += e[j]; }
#pragma unroll
    for (int o = 16; o; o >>= 1) s += __shfl_xor_sync(0xffffffffu, s, o);
    if (lane == 0) redsum[warp] = s;
    __syncthreads();
    float bs = 0.f;
#pragma unroll
    for (int w = 0; w < 8; w++) bs += redsum[w];
    float inv = 1.0f / bs;

    unsigned* prow = reinterpret_cast<unsigned*>(srow);
#pragma unroll
    for (int j = 0; j < 8; j++) {
        float p = e[j] * inv * mrow[t + 256 * j];
        prow[t + 256 * j] = split_pack(p);
    }
}

// ---------------- generic split-bf16 GEMM ----------------
// C[M,N] = sum_k A[m,k] * (BT ? Bm[n,k] : Bm[k,n]),  A/Bm packed bf16x2, fp32 accum.
// MODE 0: store f32 C.  MODE 1: store packed bf16x2 split.  MODE 2: +bias, store f32.
template <bool BT_> struct BLayoutSel { using type = wmma::row_major; };
template <> struct BLayoutSel<true>   { using type = wmma::col_major; };

constexpr int BM = 128, BN = 128, BK = 64;
constexpr int LDA_S = BK + 8;                         // 72
constexpr int ANUM = BM * LDA_S;                      // 9216 bf16
constexpr unsigned SMEM_BYTES = 73728;

template <int MODE, bool BT>
__global__ void __launch_bounds__(256) gemm_bf16x2(
    const __nv_bfloat162* __restrict__ A, int lda, size_t strA,
    const __nv_bfloat162* __restrict__ Bm, int ldb, size_t strB,
    void* __restrict__ Cv, int ldc, size_t strC,
    const float* __restrict__ bias, int Kdim) {
    extern __shared__ __nv_bfloat16 smem[];
    const int LDB_S = BT ? (BK + 8) : (BN + 8);
    const int BNUM = BT ? BN * (BK + 8) : BK * (BN + 8);
    __nv_bfloat16* As_hi = smem;
    __nv_bfloat16* As_lo = smem + ANUM;
    __nv_bfloat16* Bs_hi = smem + 2 * ANUM;
    __nv_bfloat16* Bs_lo = smem + 2 * ANUM + BNUM;

    const int b = blockIdx.z;
    const __nv_bfloat162* Ab = A + (size_t)b * strA;
    const __nv_bfloat162* Bb = Bm + (size_t)b * strB;
    const int m0 = blockIdx.y * BM;
    const int n0 = blockIdx.x * BN;

    const int tid = threadIdx.x;
    const int lane = tid & 31;
    const int wid = tid >> 5;
    const int wm = wid >> 1; // 0..3 (32 rows each)
    const int wn = wid & 1;  // 0..1 (64 cols each)

    wmma::fragment<wmma::accumulator, 16, 16, 16, float> acc[2][4];
#pragma unroll
    for (int i = 0; i < 2; i++)
#pragma unroll
        for (int j = 0; j < 4; j++) wmma::fill_fragment(acc[i][j], 0.f);

    using BLay = typename BLayoutSel<BT>::type;

    for (int k0 = 0; k0 < Kdim; k0 += BK) {
        // ---- load A tile: 128 x 64 packed (uint4 = 4 packed elems) ----
#pragma unroll
        for (int it = 0; it < 8; it++) {
            int idx = tid + it * 256;
            int r = idx >> 4, c = (idx & 15) << 2;
            uint4 v = *reinterpret_cast<const uint4*>(Ab + (size_t)(m0 + r) * lda + k0 + c);
            uint2 hi, lo;
            hi.x = __byte_perm(v.x, v.y, 0x5410);
            hi.y = __byte_perm(v.z, v.w, 0x5410);
            lo.x = __byte_perm(v.x, v.y, 0x7632);
            lo.y = __byte_perm(v.z, v.w, 0x7632);
            *reinterpret_cast<uint2*>(As_hi + r * LDA_S + c) = hi;
            *reinterpret_cast<uint2*>(As_lo + r * LDA_S + c) = lo;
        }
        // ---- load B tile ----
#pragma unroll
        for (int it = 0; it < 8; it++) {
            int idx = tid + it * 256;
            int r, c;
            const __nv_bfloat162* gp;
            if (BT) { r = idx >> 4; c = (idx & 15) << 2; gp = Bb + (size_t)(n0 + r) * ldb + k0 + c; }
            else    { r = idx >> 5; c = (idx & 31) << 2; gp = Bb + (size_t)(k0 + r) * ldb + n0 + c; }
            uint4 v = *reinterpret_cast<const uint4*>(gp);
            uint2 hi, lo;
            hi.x = __byte_perm(v.x, v.y, 0x5410);
            hi.y = __byte_perm(v.z, v.w, 0x5410);
            lo.x = __byte_perm(v.x, v.y, 0x7632);
            lo.y = __byte_perm(v.z, v.w, 0x7632);
            *reinterpret_cast<uint2*>(Bs_hi + r * LDB_S + c) = hi;
            *reinterpret_cast<uint2*>(Bs_lo + r * LDB_S + c) = lo;
        }
        __syncthreads();

#pragma unroll
        for (int kk = 0; kk < BK; kk += 16) {
            wmma::fragment<wmma::matrix_a, 16, 16, 16, __nv_bfloat16, wmma::row_major> ah[2], al[2];
#pragma unroll
            for (int i = 0; i < 2; i++) {
                int row = wm * 32 + i * 16;
                wmma::load_matrix_sync(ah[i], As_hi + row * LDA_S + kk, LDA_S);
                wmma::load_matrix_sync(al[i], As_lo + row * LDA_S + kk, LDA_S);
            }
            wmma::fragment<wmma::matrix_b, 16, 16, 16, __nv_bfloat16, BLay> bh[4], bl[4];
#pragma unroll
            for (int j = 0; j < 4; j++) {
                int col = wn * 64 + j * 16;
                const __nv_bfloat16 *ph, *pl;
                if (BT) { ph = Bs_hi + col * LDB_S + kk; pl = Bs_lo + col * LDB_S + kk; }
                else    { ph = Bs_hi + kk * LDB_S + col; pl = Bs_lo + kk * LDB_S + col; }
                wmma::load_matrix_sync(bh[j], ph, LDB_S);
                wmma::load_matrix_sync(bl[j], pl, LDB_S);
            }
#pragma unroll
            for (int i = 0; i < 2; i++)
#pragma unroll
                for (int j = 0; j < 4; j++) {
                    wmma::mma_sync(acc[i][j], ah[i], bh[j], acc[i][j]);
                    wmma::mma_sync(acc[i][j], ah[i], bl[j], acc[i][j]);
                    wmma::mma_sync(acc[i][j], al[i], bh[j], acc[i][j]);
                }
        }
        __syncthreads();
    }

    // ---------------- epilogue ----------------
    if (MODE == 0) {
        float* C = reinterpret_cast<float*>(Cv) + (size_t)b * strC;
#pragma unroll
        for (int i = 0; i < 2; i++)
#pragma unroll
            for (int j = 0; j < 4; j++) {
                int gr = m0 + wm * 32 + i * 16;
                int gc = n0 + wn * 64 + j * 16;
                wmma::store_matrix_sync(C + (size_t)gr * ldc + gc, acc[i][j], ldc,
                                        wmma::mem_row_major);
            }
    } else {
        // stage through smem (safe: mainloop ended on __syncthreads)
        float* stage = reinterpret_cast<float*>(smem) + wid * (32 * 72);
#pragma unroll
        for (int i = 0; i < 2; i++)
#pragma unroll
            for (int j = 0; j < 4; j++)
                wmma::store_matrix_sync(stage + i * 16 * 72 + j * 16, acc[i][j], 72,
                                        wmma::mem_row_major);
        __syncwarp();
        int wr0 = m0 + wm * 32, wc0 = n0 + wn * 64;
#pragma unroll
        for (int it = 0; it < 16; it++) {
            int idx = lane + it * 32;
            int r = idx >> 4, c = (idx & 15) << 2;
            float4 v = *reinterpret_cast<float4*>(stage + r * 72 + c);
            int gr = wr0 + r, gc = wc0 + c;
            if (MODE == 2) {
                v.x += bias[gc]; v.y += bias[gc + 1]; v.z += bias[gc + 2]; v.w += bias[gc + 3];
                float* C = reinterpret_cast<float*>(Cv);
                *reinterpret_cast<float4*>(C + (size_t)gr * ldc + gc) = v;
            } else {
                unsigned* C = reinterpret_cast<unsigned*>(Cv) + (size_t)b * strC;
                uint4 o;
                o.x = split_pack(v.x); o.y = split_pack(v.y);
                o.z = split_pack(v.z); o.w = split_pack(v.w);
                *reinterpret_cast<uint4*>(C + (size_t)gr * ldc + gc) = o;
            }
        }
    }
}

// ---------------- launch ----------------
extern "C" void kernel_launch(void* const* d_in, const int* in_sizes, int n_in,
                              void* d_out, int out_size) {
    const float* Q    = (const float*)d_in[0];
    const float* Kx   = (const float*)d_in[1];
    const float* V    = (const float*)d_in[2];
    const float* mask = (const float*)d_in[3];
    const float* W    = (const float*)d_in[4];
    const float* bias = (const float*)d_in[5];
    const int*   inv  = (const int*)d_in[6];

    void *pQ, *pK, *pV, *pW, *pS;
    cudaGetSymbolAddress(&pQ, g_Q);
    cudaGetSymbolAddress(&pK, g_K);
    cudaGetSymbolAddress(&pV, g_V);
    cudaGetSymbolAddress(&pW, g_W);
    cudaGetSymbolAddress(&pS, g_scores);

    __nv_bfloat162* Qs = (__nv_bfloat162*)pQ;
    __nv_bfloat162* Ks = (__nv_bfloat162*)pK;
    __nv_bfloat162* Vs = (__nv_bfloat162*)pV;
    __nv_bfloat162* Ws = (__nv_bfloat162*)pW;
    float*          Sc = (float*)pS;
    __nv_bfloat162* Pr = (__nv_bfloat162*)pS;  // probs alias scores (in-place rewrite)
    __nv_bfloat162* At = (__nv_bfloat162*)pQ;  // attn reuses Q split buffer (Q dead after GEMM1)

    cudaFuncSetAttribute(gemm_bf16x2<0, true>,
                         cudaFuncAttributeMaxDynamicSharedMemorySize, SMEM_BYTES);
    cudaFuncSetAttribute(gemm_bf16x2<1, false>,
                         cudaFuncAttributeMaxDynamicSharedMemorySize, SMEM_BYTES);
    cudaFuncSetAttribute(gemm_bf16x2<2, true>,
                         cudaFuncAttributeMaxDynamicSharedMemorySize, SMEM_BYTES);

    // splits: f32 -> packed bf16 hi/lo
    int n4 = B_ * S_ * E_ / 4;
    split_kernel<<<(n4 + 255) / 256, 256>>>(Q,  (unsigned*)Qs, n4);
    split_kernel<<<(n4 + 255) / 256, 256>>>(Kx, (unsigned*)Ks, n4);
    split_kernel<<<(n4 + 255) / 256, 256>>>(V,  (unsigned*)Vs, n4);
    int w4 = E_ * E_ / 4;
    split_kernel<<<(w4 + 255) / 256, 256>>>(W,  (unsigned*)Ws, w4);

    // GEMM1: scores = Q @ K^T   (scale applied inside softmax)
    dim3 g1(S_ / BN, S_ / BM, B_);
    gemm_bf16x2<0, true><<<g1, 256, SMEM_BYTES>>>(
        Qs, E_, (size_t)S_ * E_, Ks, E_, (size_t)S_ * E_,
        Sc, S_, (size_t)S_ * S_, nullptr, E_);

    // softmax(scale*scores) * mask -> packed probs, in place
    softmax_mask_kernel<<<B_ * S_, 256>>>(Sc, mask, inv);

    // GEMM2: attn = probs @ V
    dim3 g2(E_ / BN, S_ / BM, B_);
    gemm_bf16x2<1, false><<<g2, 256, SMEM_BYTES>>>(
        Pr, S_, (size_t)S_ * S_, Vs, E_, (size_t)S_ * E_,
        At, E_, (size_t)S_ * E_, nullptr, S_);

    // GEMM3: out = attn @ W^T + bias
    dim3 g3(E_ / BN, (B_ * S_) / BM, 1);
    gemm_bf16x2<2, true><<<g3, 256, SMEM_BYTES>>>(
        At, E_, 0, Ws, E_, 0,
        d_out, E_, 0, bias, E_);
}

// round 5
// speedup vs baseline: 1.3021x; 1.3021x over previous
#include <cuda_runtime.h>
#include <cuda_bf16.h>
#include <cstdint>
#include <cstddef>
#include <mma.h>

using namespace nvcuda;

#define B_ 8
#define S_ 2048
#define E_ 1024

// ================= scratch (device globals; allocation-free rule) =================
__device__ __nv_bfloat16 g_Qhi[(size_t)B_ * S_ * E_];
__device__ __nv_bfloat16 g_Qlo[(size_t)B_ * S_ * E_];
__device__ __nv_bfloat16 g_Khi[(size_t)B_ * S_ * E_];
__device__ __nv_bfloat16 g_Klo[(size_t)B_ * S_ * E_];
__device__ __nv_bfloat16 g_Vthi[(size_t)B_ * E_ * S_];  // V transposed: [B, E, S]
__device__ __nv_bfloat16 g_Vtlo[(size_t)B_ * E_ * S_];
__device__ __nv_bfloat16 g_Whi[(size_t)E_ * E_];
__device__ __nv_bfloat16 g_Wlo[(size_t)E_ * E_];
__device__ float         g_scores[(size_t)B_ * S_ * S_];
__device__ __nv_bfloat16 g_Phi[(size_t)B_ * S_ * S_];
__device__ __nv_bfloat16 g_Plo[(size_t)B_ * S_ * S_];
// attn split reuses g_Qhi/g_Qlo (Q dead after GEMM1)

// ================= async-copy helpers =================
__device__ __forceinline__ uint32_t smem_u32(const void* p) {
    uint32_t a;
    asm("{ .reg .u64 t; cvta.to.shared.u64 t, %1; cvt.u32.u64 %0, t; }" : "=r"(a) : "l"(p));
    return a;
}
__device__ __forceinline__ void cp16(uint32_t dst, const void* src) {
    asm volatile("cp.async.cg.shared.global [%0], [%1], 16;" :: "r"(dst), "l"(src) : "memory");
}
__device__ __forceinline__ void cp_commit() { asm volatile("cp.async.commit_group;" ::: "memory"); }
__device__ __forceinline__ void cp_wait1()  { asm volatile("cp.async.wait_group 1;" ::: "memory"); }

// ================= split kernels =================
__global__ void __launch_bounds__(256) split_plane(const float* __restrict__ x,
                                                   __nv_bfloat16* __restrict__ hi,
                                                   __nv_bfloat16* __restrict__ lo, int n8) {
    int i = blockIdx.x * blockDim.x + threadIdx.x;
    if (i >= n8) return;
    const float4* x4 = reinterpret_cast<const float4*>(x) + (size_t)i * 2;
    float4 a = x4[0], b = x4[1];
    float f[8] = {a.x, a.y, a.z, a.w, b.x, b.y, b.z, b.w};
    __nv_bfloat16 h[8], l[8];
#pragma unroll
    for (int j = 0; j < 8; j++) {
        h[j] = __float2bfloat16(f[j]);
        l[j] = __float2bfloat16(f[j] - __bfloat162float(h[j]));
    }
    *reinterpret_cast<uint4*>(hi + (size_t)i * 8) = *reinterpret_cast<const uint4*>(h);
    *reinterpret_cast<uint4*>(lo + (size_t)i * 8) = *reinterpret_cast<const uint4*>(l);
}

// V [B,S,E] f32 -> transposed planes [B,E,S] bf16 hi/lo
__global__ void __launch_bounds__(256) splitT_v(const float* __restrict__ v,
                                                __nv_bfloat16* __restrict__ hi,
                                                __nv_bfloat16* __restrict__ lo) {
    __shared__ float tile[32][33];
    int b = blockIdx.z;
    int s0 = blockIdx.x * 32, e0 = blockIdx.y * 32;
    int tx = threadIdx.x & 31, ty = threadIdx.x >> 5;
    const float* vb = v + (size_t)b * S_ * E_;
#pragma unroll
    for (int k = 0; k < 4; k++)
        tile[ty + 8 * k][tx] = vb[(size_t)(s0 + ty + 8 * k) * E_ + e0 + tx];
    __syncthreads();
    __nv_bfloat16* hb = hi + (size_t)b * E_ * S_;
    __nv_bfloat16* lb = lo + (size_t)b * E_ * S_;
#pragma unroll
    for (int k = 0; k < 4; k++) {
        float f = tile[tx][ty + 8 * k];
        __nv_bfloat16 h = __float2bfloat16(f);
        size_t o = (size_t)(e0 + ty + 8 * k) * S_ + s0 + tx;
        hb[o] = h;
        lb[o] = __float2bfloat16(f - __bfloat162float(h));
    }
}

// ================= softmax * mask -> planar bf16 hi/lo probs =================
__global__ void __launch_bounds__(256) softmax_mask_kernel(
    const float* __restrict__ scores, const float* __restrict__ mask,
    __nv_bfloat16* __restrict__ phi, __nv_bfloat16* __restrict__ plo,
    const int* __restrict__ sc) {
    __shared__ float redmax[8], redsum[8];
    size_t row = blockIdx.x;
    const float* srow = scores + row * (size_t)S_;
    const float* mrow = mask + row * (size_t)S_;
    int t = threadIdx.x, lane = t & 31, warp = t >> 5;

    int iv = *sc;
    float denom = (iv == 32) ? 32.0f : __int_as_float(iv);
    float scale = 1.0f / denom;

    float v[8];
#pragma unroll
    for (int j = 0; j < 8; j++) v[j] = srow[t + 256 * j] * scale;
    float m = v[0];
#pragma unroll
    for (int j = 1; j < 8; j++) m = fmaxf(m, v[j]);
#pragma unroll
    for (int o = 16; o; o >>= 1) m = fmaxf(m, __shfl_xor_sync(0xffffffffu, m, o));
    if (lane == 0) redmax[warp] = m;
    __syncthreads();
    float bm = redmax[0];
#pragma unroll
    for (int w = 1; w < 8; w++) bm = fmaxf(bm, redmax[w]);
    float e[8], s = 0.f;
#pragma unroll
    for (int j = 0; j < 8; j++) { e[j] = __expf(v[j] - bm); s += e[j]; }
#pragma unroll
    for (int o = 16; o; o >>= 1) s += __shfl_xor_sync(0xffffffffu, s, o);
    if (lane == 0) redsum[warp] = s;
    __syncthreads();
    float bs = 0.f;
#pragma unroll
    for (int w = 0; w < 8; w++) bs += redsum[w];
    float inv = 1.0f / bs;

    __nv_bfloat16* ph = phi + row * (size_t)S_;
    __nv_bfloat16* pl = plo + row * (size_t)S_;
#pragma unroll
    for (int j = 0; j < 8; j++) {
        float p = e[j] * inv * mrow[t + 256 * j];
        __nv_bfloat16 h = __float2bfloat16(p);
        ph[t + 256 * j] = h;
        pl[t + 256 * j] = __float2bfloat16(p - __bfloat162float(h));
    }
}

// ================= pipelined split-bf16 WMMA NT GEMM =================
// C[M,N] = sum_k A[m,k]*B[n,k]; A/B planar hi/lo bf16, fp32 accum via HMMA.
// MODE 0: f32 out. MODE 1: planar bf16 hi/lo out. MODE 2: f32 + bias out.
constexpr int BM = 128, BN = 128, BK = 64;
constexpr int PITCH = 72;                       // BK + 8 pad (bf16 elems)
constexpr int PLANEB = BM * PITCH * 2;          // 18432 B per plane tile
constexpr int STAGEB = 4 * PLANEB;              // Ahi/Alo/Bhi/Blo = 73728 B
constexpr int STAGES = 3;
constexpr unsigned GSMEM = STAGES * STAGEB;     // 221184 B

template <int MODE>
__global__ void __launch_bounds__(256) gemm_pipe(
    const __nv_bfloat16* __restrict__ Ahi, const __nv_bfloat16* __restrict__ Alo,
    int lda, size_t strA,
    const __nv_bfloat16* __restrict__ Bhi, const __nv_bfloat16* __restrict__ Blo,
    int ldb, size_t strB,
    void* __restrict__ C0, void* __restrict__ C1, int ldc, size_t strC,
    const float* __restrict__ bias, int Kdim) {
    extern __shared__ __nv_bfloat16 smem[];
    const uint32_t sbase = smem_u32(smem);
    const int tid = threadIdx.x;
    const int lane = tid & 31, wid = tid >> 5;
    const int wm = wid >> 1;                 // 0..3  (32-row strips)
    const int wn = wid & 1;                  // 0..1  (64-col strips)
    const int b = blockIdx.z;
    const int m0 = blockIdx.y * BM, n0 = blockIdx.x * BN;

    const __nv_bfloat16* pa[2] = {Ahi + (size_t)b * strA, Alo + (size_t)b * strA};
    const __nv_bfloat16* pb[2] = {Bhi + (size_t)b * strB, Blo + (size_t)b * strB};

    const int niter = Kdim / BK;

    // stage loader: 4 planes x (128 rows x 64 bf16) with cp.async 16B chunks
    auto load_stage = [&](int j) {
        const int k0 = j * BK;
        const uint32_t sb = sbase + (j % STAGES) * STAGEB;
#pragma unroll
        for (int p = 0; p < 4; p++) {
            const __nv_bfloat16* src = (p < 2) ? pa[p] : pb[p - 2];
            const int r0 = (p < 2) ? m0 : n0;
            const int ld = (p < 2) ? lda : ldb;
#pragma unroll
            for (int it = 0; it < 4; it++) {
                int id = tid + it * 256;          // 1024 chunks
                int r = id >> 3, c = id & 7;      // 128 rows x 8 x 16B
                uint32_t dst = sb + (uint32_t)p * PLANEB + (uint32_t)(r * PITCH * 2 + c * 16);
                cp16(dst, src + (size_t)(r0 + r) * ld + k0 + c * 8);
            }
        }
    };

    wmma::fragment<wmma::accumulator, 16, 16, 16, float> acc[2][4];
#pragma unroll
    for (int i = 0; i < 2; i++)
#pragma unroll
        for (int j = 0; j < 4; j++) wmma::fill_fragment(acc[i][j], 0.f);

    // prologue
    load_stage(0); cp_commit();
    load_stage(1); cp_commit();

    for (int i = 0; i < niter; i++) {
        cp_wait1();          // stage i resident (only stage i+1 may still be in flight)
        __syncthreads();

        // prefetch stage i+2 (overwrites buffer of stage i-1; safe past the barrier)
        if (i + 2 < niter) load_stage(i + 2);
        cp_commit();

        // compute stage i
        const __nv_bfloat16* As_hi =
            smem + (size_t)(i % STAGES) * (STAGEB / 2);
        const __nv_bfloat16* As_lo = As_hi + PLANEB / 2;
        const __nv_bfloat16* Bs_hi = As_hi + 2 * (PLANEB / 2);
        const __nv_bfloat16* Bs_lo = As_hi + 3 * (PLANEB / 2);

#pragma unroll
        for (int kk = 0; kk < BK; kk += 16) {
            wmma::fragment<wmma::matrix_a, 16, 16, 16, __nv_bfloat16, wmma::row_major> ah[2], al[2];
#pragma unroll
            for (int x = 0; x < 2; x++) {
                int row = wm * 32 + x * 16;
                wmma::load_matrix_sync(ah[x], As_hi + row * PITCH + kk, PITCH);
                wmma::load_matrix_sync(al[x], As_lo + row * PITCH + kk, PITCH);
            }
            wmma::fragment<wmma::matrix_b, 16, 16, 16, __nv_bfloat16, wmma::col_major> bh[4], bl[4];
#pragma unroll
            for (int y = 0; y < 4; y++) {
                int col = wn * 64 + y * 16;
                wmma::load_matrix_sync(bh[y], Bs_hi + col * PITCH + kk, PITCH);
                wmma::load_matrix_sync(bl[y], Bs_lo + col * PITCH + kk, PITCH);
            }
#pragma unroll
            for (int x = 0; x < 2; x++)
#pragma unroll
                for (int y = 0; y < 4; y++) {
                    wmma::mma_sync(acc[x][y], ah[x], bh[y], acc[x][y]);
                    wmma::mma_sync(acc[x][y], ah[x], bl[y], acc[x][y]);
                    wmma::mma_sync(acc[x][y], al[x], bh[y], acc[x][y]);
                }
        }
        __syncthreads();
    }

    // ---------------- epilogue ----------------
    if (MODE == 0) {
        float* C = reinterpret_cast<float*>(C0) + (size_t)b * strC;
#pragma unroll
        for (int x = 0; x < 2; x++)
#pragma unroll
            for (int y = 0; y < 4; y++) {
                int gr = m0 + wm * 32 + x * 16;
                int gc = n0 + wn * 64 + y * 16;
                wmma::store_matrix_sync(C + (size_t)gr * ldc + gc, acc[x][y], ldc,
                                        wmma::mem_row_major);
            }
    } else {
        // stage accumulators through smem for coalesced stores (stage buffers dead)
        float* stage = reinterpret_cast<float*>(smem) + wid * (32 * 72);
#pragma unroll
        for (int x = 0; x < 2; x++)
#pragma unroll
            for (int y = 0; y < 4; y++)
                wmma::store_matrix_sync(stage + x * 16 * 72 + y * 16, acc[x][y], 72,
                                        wmma::mem_row_major);
        __syncwarp();
        int wr0 = m0 + wm * 32, wc0 = n0 + wn * 64;
#pragma unroll
        for (int it = 0; it < 16; it++) {
            int idx = lane + it * 32;
            int r = idx >> 4, c = (idx & 15) << 2;
            float4 v = *reinterpret_cast<float4*>(stage + r * 72 + c);
            int gr = wr0 + r, gc = wc0 + c;
            if (MODE == 2) {
                v.x += bias[gc]; v.y += bias[gc + 1]; v.z += bias[gc + 2]; v.w += bias[gc + 3];
                float* C = reinterpret_cast<float*>(C0);
                *reinterpret_cast<float4*>(C + (size_t)gr * ldc + gc) = v;
            } else {
                __nv_bfloat16* Ch = reinterpret_cast<__nv_bfloat16*>(C0) + (size_t)b * strC;
                __nv_bfloat16* Cl = reinterpret_cast<__nv_bfloat16*>(C1) + (size_t)b * strC;
                float f[4] = {v.x, v.y, v.z, v.w};
                __nv_bfloat16 h[4], l[4];
#pragma unroll
                for (int q = 0; q < 4; q++) {
                    h[q] = __float2bfloat16(f[q]);
                    l[q] = __float2bfloat16(f[q] - __bfloat162float(h[q]));
                }
                size_t o = (size_t)gr * ldc + gc;
                *reinterpret_cast<uint2*>(Ch + o) = *reinterpret_cast<const uint2*>(h);
                *reinterpret_cast<uint2*>(Cl + o) = *reinterpret_cast<const uint2*>(l);
            }
        }
    }
}

// ================= launch =================
extern "C" void kernel_launch(void* const* d_in, const int* in_sizes, int n_in,
                              void* d_out, int out_size) {
    const float* Q    = (const float*)d_in[0];
    const float* Kx   = (const float*)d_in[1];
    const float* V    = (const float*)d_in[2];
    const float* mask = (const float*)d_in[3];
    const float* W    = (const float*)d_in[4];
    const float* bias = (const float*)d_in[5];
    const int*   inv  = (const int*)d_in[6];

    void *pQh, *pQl, *pKh, *pKl, *pVh, *pVl, *pWh, *pWl, *pS, *pPh, *pPl;
    cudaGetSymbolAddress(&pQh, g_Qhi);  cudaGetSymbolAddress(&pQl, g_Qlo);
    cudaGetSymbolAddress(&pKh, g_Khi);  cudaGetSymbolAddress(&pKl, g_Klo);
    cudaGetSymbolAddress(&pVh, g_Vthi); cudaGetSymbolAddress(&pVl, g_Vtlo);
    cudaGetSymbolAddress(&pWh, g_Whi);  cudaGetSymbolAddress(&pWl, g_Wlo);
    cudaGetSymbolAddress(&pS, g_scores);
    cudaGetSymbolAddress(&pPh, g_Phi);  cudaGetSymbolAddress(&pPl, g_Plo);

    __nv_bfloat16 *Qh = (__nv_bfloat16*)pQh, *Ql = (__nv_bfloat16*)pQl;
    __nv_bfloat16 *Kh = (__nv_bfloat16*)pKh, *Kl = (__nv_bfloat16*)pKl;
    __nv_bfloat16 *Vh = (__nv_bfloat16*)pVh, *Vl = (__nv_bfloat16*)pVl;
    __nv_bfloat16 *Wh = (__nv_bfloat16*)pWh, *Wl = (__nv_bfloat16*)pWl;
    float* Sc = (float*)pS;
    __nv_bfloat16 *Ph = (__nv_bfloat16*)pPh, *Pl = (__nv_bfloat16*)pPl;
    __nv_bfloat16 *Ath = Qh, *Atl = Ql;  // attn reuses Q planes

    cudaFuncSetAttribute(gemm_pipe<0>, cudaFuncAttributeMaxDynamicSharedMemorySize, GSMEM);
    cudaFuncSetAttribute(gemm_pipe<1>, cudaFuncAttributeMaxDynamicSharedMemorySize, GSMEM);
    cudaFuncSetAttribute(gemm_pipe<2>, cudaFuncAttributeMaxDynamicSharedMemorySize, GSMEM);

    // splits
    int n8 = B_ * S_ * E_ / 8;
    split_plane<<<(n8 + 255) / 256, 256>>>(Q, Qh, Ql, n8);
    split_plane<<<(n8 + 255) / 256, 256>>>(Kx, Kh, Kl, n8);
    int w8 = E_ * E_ / 8;
    split_plane<<<(w8 + 255) / 256, 256>>>(W, Wh, Wl, w8);
    dim3 gt(S_ / 32, E_ / 32, B_);
    splitT_v<<<gt, 256>>>(V, Vh, Vl);

    // GEMM1: scores = Q @ K^T  [M=S, N=S, K=E]
    dim3 g1(S_ / BN, S_ / BM, B_);
    gemm_pipe<0><<<g1, 256, GSMEM>>>(Qh, Ql, E_, (size_t)S_ * E_,
                                     Kh, Kl, E_, (size_t)S_ * E_,
                                     Sc, nullptr, S_, (size_t)S_ * S_, nullptr, E_);

    // softmax * mask -> planar probs
    softmax_mask_kernel<<<B_ * S_, 256>>>(Sc, mask, Ph, Pl, inv);

    // GEMM2: attn = P @ Vt^T   [M=S, N=E, K=S]
    dim3 g2(E_ / BN, S_ / BM, B_);
    gemm_pipe<1><<<g2, 256, GSMEM>>>(Ph, Pl, S_, (size_t)S_ * S_,
                                     Vh, Vl, S_, (size_t)E_ * S_,
                                     Ath, Atl, E_, (size_t)S_ * E_, nullptr, S_);

    // GEMM3: out = attn @ W^T + bias  [M=B*S, N=E, K=E]
    dim3 g3(E_ / BN, (B_ * S_) / BM, 1);
    gemm_pipe<2><<<g3, 256, GSMEM>>>(Ath, Atl, E_, 0,
                                     Wh, Wl, E_, 0,
                                     d_out, nullptr, E_, 0, bias, E_);
}